// round 6
// baseline (speedup 1.0000x reference)
#include <cuda_runtime.h>

#define GRID 296
#define TPB  256
#define NT   (GRID * TPB)      // 75776 threads total
#define MAXB 1048576

__device__ float4 g_hn[MAXB];              // cached layer-norm outputs (pass A -> pass B)
__device__ float  g_partials[GRID * 16];   // per-block [8 sums, 8 sumsq]

__device__ __forceinline__ float ex2f(float x) {
    float y; asm("ex2.approx.ftz.f32 %0, %1;" : "=f"(y) : "f"(x)); return y;
}
__device__ __forceinline__ float sin_fast(float x) {
    float y; asm("sin.approx.ftz.f32 %0, %1;" : "=f"(y) : "f"(x)); return y;
}

// =======================  PASS A  =======================
__global__ __launch_bounds__(TPB, 2)
void passA(const float* __restrict__ xg,
           const float* __restrict__ W1, const float* __restrict__ b1,
           const float* __restrict__ gam, const float* __restrict__ bet,
           const float* __restrict__ mIn, const float* __restrict__ th,
           int n)
{
    __shared__ float prm[64];
    __shared__ float stage[8 * 320];   // 8 warps x 32 rows x 10 floats

    const int tid = threadIdx.x, bid = blockIdx.x;
    const int wid = tid >> 5, lane = tid & 31;

    if      (tid < 30) prm[tid] = W1[tid];
    else if (tid < 33) prm[tid] = b1[tid - 30];
    else if (tid < 36) prm[tid] = gam[tid - 33];
    else if (tid < 39) prm[tid] = bet[tid - 36];
    else if (tid < 45) prm[tid] = mIn[tid - 39];
    else if (tid < 51) { const float t = th[tid - 45];
                         prm[tid] = -1.4426950408889634f / (2.0f * t * t); }
    __syncthreads();

    // hoist all params into registers (no smem writes in mainloop -> stays hoisted)
    float w1[30], bb1[3], gm[3], bt[3], mv[6], c2[6];
#pragma unroll
    for (int i = 0; i < 30; i++) w1[i] = prm[i];
#pragma unroll
    for (int i = 0; i < 3; i++) { bb1[i] = prm[30 + i]; gm[i] = prm[33 + i]; bt[i] = prm[36 + i]; }
#pragma unroll
    for (int i = 0; i < 6; i++) { mv[i] = prm[39 + i]; c2[i] = prm[45 + i]; }

    float* buf = stage + wid * 320;
    const float C2 = 0.99999f * 0.99999f;
    const int iters = (n + NT - 1) / NT;

    float acc[16];
#pragma unroll
    for (int i = 0; i < 16; i++) acc[i] = 0.f;

    for (int k = 0; k < iters; k++) {
        const int warpBase = bid * TPB + wid * 32 + k * NT;
        if (warpBase < n) {
            // coalesced stage: 320 floats (32 rows) per warp
            const float* src = xg + (size_t)warpBase * 10;
            const int lim = min(320, (n - warpBase) * 10);
#pragma unroll
            for (int j = 0; j < 10; j++) {
                const int idx = j * 32 + lane;
                if (idx < lim) buf[idx] = src[idx];
            }
        }
        __syncwarp();
        const int r = warpBase + lane;
        if (r < n) {
            float xv[10];
            const float2* bp2 = (const float2*)(buf + lane * 10);
#pragma unroll
            for (int j = 0; j < 5; j++) { const float2 v = bp2[j]; xv[2*j] = v.x; xv[2*j+1] = v.y; }

            float h[3];
#pragma unroll
            for (int q = 0; q < 3; q++) {
                float a = bb1[q];
#pragma unroll
                for (int c = 0; c < 10; c++) a = fmaf(xv[c], w1[q * 10 + c], a);
                h[q] = a;
            }
            const float mu = (h[0] + h[1] + h[2]) * (1.0f / 3.0f);
            const float d0 = h[0] - mu, d1 = h[1] - mu, d2 = h[2] - mu;
            const float var = (d0 * d0 + d1 * d1 + d2 * d2) * (1.0f / 3.0f);
            const float rn = rsqrtf(var + 1e-5f);
            const float hn0 = fmaf(d0 * rn, gm[0], bt[0]);
            const float hn1 = fmaf(d1 * rn, gm[1], bt[1]);
            const float hn2 = fmaf(d2 * rn, gm[2], bt[2]);
            g_hn[r] = make_float4(hn0, hn1, hn2, 0.f);

            float p[6];
#pragma unroll
            for (int kk = 0; kk < 6; kk++) {
                const float hq = (kk < 2) ? hn0 : (kk < 4) ? hn1 : hn2;
                const float a = hq - mv[kk];
                const float f = ex2f(a * a * c2[kk]);
                const float pv = fminf(f + 1e-16f, C2);
                p[kk] = (kk < 2) ? pv : (1.0f - pv);
            }
            const float w00 = p[2] * p[4], w01 = p[2] * p[5];
            const float w10 = p[3] * p[4], w11 = p[3] * p[5];
            float o[8];
            o[0] = p[0] * w00; o[1] = p[0] * w01; o[2] = p[0] * w10; o[3] = p[0] * w11;
            o[4] = p[1] * w00; o[5] = p[1] * w01; o[6] = p[1] * w10; o[7] = p[1] * w11;
#pragma unroll
            for (int c = 0; c < 8; c++) {
                acc[c] += o[c];
                acc[8 + c] = fmaf(o[c], o[c], acc[8 + c]);
            }
        }
        __syncwarp();
    }

    // deterministic block reduction
    __syncthreads();
    float* red = stage;
#pragma unroll
    for (int kk = 0; kk < 16; kk++) {
        float v = acc[kk];
#pragma unroll
        for (int off = 16; off; off >>= 1)
            v += __shfl_down_sync(0xffffffffu, v, off);
        if (lane == 0) red[wid * 16 + kk] = v;
    }
    __syncthreads();
    if (tid < 16) {
        float s = 0.f;
#pragma unroll
        for (int w = 0; w < 8; w++) s += red[w * 16 + tid];
        g_partials[bid * 16 + tid] = s;
    }
}

// =======================  PASS B  =======================
__global__ __launch_bounds__(TPB, 2)
void passB(float* __restrict__ outg,
           const float* __restrict__ mIn, const float* __restrict__ th,
           const float* __restrict__ g2, const float* __restrict__ bt2,
           const float* __restrict__ W2, const float* __restrict__ b2,
           int n)
{
    __shared__ float prm[64];   // m 0..5, c2 6..11, W2 12..35, b2 36..38, g2 39..46, bt2 47..54
    __shared__ float red[272];
    __shared__ float scs[8], t2s[8], bps[4];

    const int tid = threadIdx.x, bid = blockIdx.x;

    if      (tid < 6)  prm[tid] = mIn[tid];
    else if (tid < 12) { const float t = th[tid - 6];
                         prm[tid] = -1.4426950408889634f / (2.0f * t * t); }
    else if (tid < 36) prm[tid] = W2[tid - 12];     // rows 0..2 of W2 = first 24 elems
    else if (tid < 39) prm[tid] = b2[tid - 36];
    else if (tid < 47) prm[tid] = g2[tid - 39];
    else if (tid < 55) prm[tid] = bt2[tid - 47];
    __syncthreads();

    // every block folds the partials identically (deterministic, tiny, L2-hit)
    {
        const int met = tid & 15, ch = tid >> 4;
        float s = 0.f;
#pragma unroll 4
        for (int i = 0; i < 19; i++) {
            const int b = ch * 19 + i;
            if (b < GRID) s += g_partials[b * 16 + met];
        }
        red[tid] = s;
    }
    __syncthreads();
    if (tid < 16) {
        float s = 0.f;
#pragma unroll
        for (int w = 0; w < 16; w++) s += red[w * 16 + tid];
        red[256 + tid] = s;
    }
    __syncthreads();
    if (tid < 8) {
        const float invB = 1.0f / (float)n;
        const float muv = red[256 + tid] * invB;
        const float msq = red[256 + 8 + tid] * invB;
        const float var = msq - muv * muv;
        const float sc = prm[39 + tid] * rsqrtf(var + 1e-5f);
        scs[tid] = sc;
        t2s[tid] = prm[47 + tid] - muv * sc;
    }
    __syncthreads();
    if (tid < 3) {
        float a = prm[36 + tid];
#pragma unroll
        for (int c = 0; c < 8; c++) a = fmaf(t2s[c], prm[12 + tid * 8 + c], a);
        bps[tid] = a;
    }
    __syncthreads();

    // hoist into registers
    float mv[6], c2[6], w2[24], sc[8], bp[3];
#pragma unroll
    for (int i = 0; i < 6; i++) { mv[i] = prm[i]; c2[i] = prm[6 + i]; }
#pragma unroll
    for (int i = 0; i < 24; i++) w2[i] = prm[12 + i];
#pragma unroll
    for (int i = 0; i < 8; i++) sc[i] = scs[i];
#pragma unroll
    for (int i = 0; i < 3; i++) bp[i] = bps[i];

    const float C2 = 0.99999f * 0.99999f;
    const int iters = (n + NT - 1) / NT;

    for (int k = 0; k < iters; k++) {
        const int r = bid * TPB + tid + k * NT;
        if (r < n) {
            const float4 hv = g_hn[r];
            float p[6];
#pragma unroll
            for (int kk = 0; kk < 6; kk++) {
                const float hq = (kk < 2) ? hv.x : (kk < 4) ? hv.y : hv.z;
                const float a = hq - mv[kk];
                const float f = ex2f(a * a * c2[kk]);
                const float pv = fminf(f + 1e-16f, C2);
                p[kk] = (kk < 2) ? pv : (1.0f - pv);
            }
            const float w00 = p[2] * p[4], w01 = p[2] * p[5];
            const float w10 = p[3] * p[4], w11 = p[3] * p[5];
            float u[8];
            u[0] = p[0] * w00 * sc[0]; u[1] = p[0] * w01 * sc[1];
            u[2] = p[0] * w10 * sc[2]; u[3] = p[0] * w11 * sc[3];
            u[4] = p[1] * w00 * sc[4]; u[5] = p[1] * w01 * sc[5];
            u[6] = p[1] * w10 * sc[6]; u[7] = p[1] * w11 * sc[7];
            float lg[3];
#pragma unroll
            for (int i = 0; i < 3; i++) {
                float a = bp[i];
#pragma unroll
                for (int c = 0; c < 8; c++) a = fmaf(u[c], w2[i * 8 + c], a);
                lg[i] = a;
            }
            const float sg0 = sin_fast(lg[0] * 0.5f);
            const float sg1 = sin_fast(lg[1] * 0.5f);
            const float sg2 = sin_fast(lg[2] * 0.5f);
            const float pq0 = sg0 * sg0, pq1 = sg1 * sg1, pq2 = sg2 * sg2;
            const float cq0 = 1.f - pq0, cq1 = 1.f - pq1, cq2 = 1.f - pq2;
            const float tt = cq1 * cq2;
            float* dst = outg + (size_t)r * 3;
            dst[0] = cq0 * tt;
            dst[1] = pq0 * tt;
            dst[2] = cq0 * (pq1 * cq2);
        }
    }
}

extern "C" void kernel_launch(void* const* d_in, const int* in_sizes, int n_in,
                              void* d_out, int out_size)
{
    const float* x = (const float*)d_in[0];
    const int n = in_sizes[0] / 10;

    passA<<<GRID, TPB>>>(x,
        (const float*)d_in[1], (const float*)d_in[2], (const float*)d_in[3],
        (const float*)d_in[4], (const float*)d_in[5], (const float*)d_in[6], n);

    passB<<<GRID, TPB>>>((float*)d_out,
        (const float*)d_in[5], (const float*)d_in[6], (const float*)d_in[7],
        (const float*)d_in[8], (const float*)d_in[9], (const float*)d_in[10], n);
}